// round 14
// baseline (speedup 1.0000x reference)
#include <cuda_runtime.h>
#include <cstdint>

#define N_NODES 50000
#define N_EDGES 800000
#define N_E2    850000      // edges + self loops
#define IN_DIM  128
#define HID     64
#define HEADS   4
#define HC      256         // HEADS*HID
#define NEG_SLOPE 0.2f
#define N_SCAN_BLK 196      // ceil(50000/256)

// ---------------- scratch (device globals; no runtime alloc) ----------------
__device__ float    g_xl1[N_NODES * HC];
__device__ float    g_xr1[N_NODES * HC];
__device__ int      g_deg[N_NODES];
__device__ int      g_start[N_NODES];
__device__ int      g_cursor[N_NODES];
__device__ int      g_blksum[256];
__device__ int      g_blkoff[256];
__device__ float4   g_csr[N_E2];          // {src(bits), a0, a1, a2}
__device__ float    g_hl2[N_NODES];
__device__ float    g_hr2[N_NODES];
__device__ float    g_out2[N_NODES];
__device__ float    g_attr_sum[3];
__device__ float    g_ssum;

// ---------------- helpers ----------------
__device__ __forceinline__ float warp_sum(float v) {
    #pragma unroll
    for (int o = 16; o; o >>= 1) v += __shfl_down_sync(0xffffffffu, v, o);
    return v;
}
__device__ __forceinline__ float warp_sum_all(float v) {
    #pragma unroll
    for (int o = 16; o; o >>= 1) v += __shfl_xor_sync(0xffffffffu, v, o);
    return v;
}
__device__ __forceinline__ float lrelu(float m) {
    return fmaxf(m, NEG_SLOPE * m);
}

// ---------------- init (deg=1 accounts for the self-loop) ----------------
__global__ void k_zero() {
    int tid = blockIdx.x * blockDim.x + threadIdx.x;
    int stride = gridDim.x * blockDim.x;
    for (int i = tid; i < N_NODES; i += stride) {
        g_deg[i] = 1; g_hl2[i] = 0.f; g_hr2[i] = 0.f;
    }
    if (tid == 0) {
        g_attr_sum[0] = 0.f; g_attr_sum[1] = 0.f; g_attr_sum[2] = 0.f;
        g_ssum = 0.f;
    }
}

// edge sweep: attr column sums + degree histogram (1 edge/thread)
__global__ void k_prep(const float* __restrict__ ea, const int* __restrict__ ei) {
    float s0 = 0.f, s1 = 0.f, s2 = 0.f;
    int e = blockIdx.x * blockDim.x + threadIdx.x;
    if (e < N_EDGES) {
        s0 = ea[e * 3 + 0]; s1 = ea[e * 3 + 1]; s2 = ea[e * 3 + 2];
        atomicAdd(&g_deg[ei[N_EDGES + e]], 1);
    }
    s0 = warp_sum(s0); s1 = warp_sum(s1); s2 = warp_sum(s2);
    if ((threadIdx.x & 31) == 0) {
        atomicAdd(&g_attr_sum[0], s0);
        atomicAdd(&g_attr_sum[1], s1);
        atomicAdd(&g_attr_sum[2], s2);
    }
}

// ---------------- SGEMM (R8 form, measured 152.6us): C = A @ B ----------------
// bx<4: C=g_xl1, B=W1l ; bx>=4: C=g_xr1, B=W1r. BM=128 BN=64 BK=16, 8x4/thr.
__global__ __launch_bounds__(256) void k_gemm(const float* __restrict__ A,
                                              const float* __restrict__ W1l,
                                              const float* __restrict__ W1r) {
    __shared__ float As[16][132];
    __shared__ float Bs[16][64];
    const int K = IN_DIM, M = HC;
    int bx = blockIdx.x;
    const float* B = (bx < 4) ? W1l : W1r;
    float* C = (bx < 4) ? g_xl1 : g_xr1;
    int row0 = blockIdx.y * 128, col0 = (bx & 3) * 64;
    int tid = threadIdx.x;
    int tr = tid >> 4, tc = tid & 15;
    float acc[8][4] = {};
    for (int k0 = 0; k0 < K; k0 += 16) {
        #pragma unroll
        for (int i = tid; i < 512; i += 256) {
            int m = i >> 2, kq = (i & 3) * 4;
            int r = row0 + m;
            float4 v = (r < N_NODES)
                ? *reinterpret_cast<const float4*>(&A[(size_t)r * K + k0 + kq])
                : make_float4(0.f, 0.f, 0.f, 0.f);
            As[kq + 0][m] = v.x; As[kq + 1][m] = v.y;
            As[kq + 2][m] = v.z; As[kq + 3][m] = v.w;
        }
        {
            int kk = tid >> 4, nq = (tid & 15) * 4;
            *reinterpret_cast<float4*>(&Bs[kk][nq]) =
                *reinterpret_cast<const float4*>(&B[(size_t)(k0 + kk) * M + col0 + nq]);
        }
        __syncthreads();
        #pragma unroll
        for (int kk = 0; kk < 16; kk++) {
            float4 a0 = *reinterpret_cast<const float4*>(&As[kk][tr * 8]);
            float4 a1 = *reinterpret_cast<const float4*>(&As[kk][tr * 8 + 4]);
            float4 b4 = *reinterpret_cast<const float4*>(&Bs[kk][tc * 4]);
            float a[8] = {a0.x, a0.y, a0.z, a0.w, a1.x, a1.y, a1.z, a1.w};
            float b[4] = {b4.x, b4.y, b4.z, b4.w};
            #pragma unroll
            for (int u = 0; u < 8; u++)
                #pragma unroll
                for (int v = 0; v < 4; v++)
                    acc[u][v] += a[u] * b[v];
        }
        __syncthreads();
    }
    #pragma unroll
    for (int u = 0; u < 8; u++) {
        int r = row0 + tr * 8 + u;
        if (r < N_NODES)
            *reinterpret_cast<float4*>(&C[(size_t)r * M + col0 + tc * 4]) =
                make_float4(acc[u][0], acc[u][1], acc[u][2], acc[u][3]);
    }
}

// parallel scan, stage 1
__global__ void k_scan1() {
    __shared__ int wTot[8];
    int tid = threadIdx.x, lane = tid & 31, wid = tid >> 5;
    int i = blockIdx.x * 256 + tid;
    int v = (i < N_NODES) ? g_deg[i] : 0;
    int x = v;
    #pragma unroll
    for (int o = 1; o < 32; o <<= 1) {
        int t = __shfl_up_sync(0xffffffffu, x, o);
        if (lane >= o) x += t;
    }
    if (lane == 31) wTot[wid] = x;
    __syncthreads();
    if (tid == 0) {
        int s = 0;
        #pragma unroll
        for (int j = 0; j < 8; j++) { int t = wTot[j]; wTot[j] = s; s += t; }
        g_blksum[blockIdx.x] = s;
    }
    __syncthreads();
    if (i < N_NODES) g_start[i] = x - v + wTot[wid];
}

// stage 2
__global__ void k_scan2() {
    __shared__ int wTot[8];
    int tid = threadIdx.x, lane = tid & 31, wid = tid >> 5;
    int v = (tid < N_SCAN_BLK) ? g_blksum[tid] : 0;
    int x = v;
    #pragma unroll
    for (int o = 1; o < 32; o <<= 1) {
        int t = __shfl_up_sync(0xffffffffu, x, o);
        if (lane >= o) x += t;
    }
    if (lane == 31) wTot[wid] = x;
    __syncthreads();
    if (tid == 0) {
        int s = 0;
        #pragma unroll
        for (int j = 0; j < 8; j++) { int t = wTot[j]; wTot[j] = s; s += t; }
    }
    __syncthreads();
    g_blkoff[tid] = x - v + wTot[wid];
}

// stage 3: finalize offsets; write the self-loop entry into reserved slot 0
__global__ void k_scan3() {
    int i = blockIdx.x * blockDim.x + threadIdx.x;
    if (i >= N_NODES) return;
    int s = g_start[i] + g_blkoff[i >> 8];
    g_start[i] = s;
    g_cursor[i] = s + 1;           // slot s holds the self-loop
    const float invE = 1.0f / N_EDGES;
    g_csr[s] = make_float4(__int_as_float(i),
                           g_attr_sum[0] * invE,
                           g_attr_sum[1] * invE,
                           g_attr_sum[2] * invE);
}

// place packed entries {src, a0, a1, a2} for real edges
__global__ void k_place(const int* __restrict__ ei, const float* __restrict__ ea) {
    int e = blockIdx.x * blockDim.x + threadIdx.x;
    if (e >= N_EDGES) return;
    int src = ei[e], dst = ei[N_EDGES + e];
    int slot = atomicAdd(&g_cursor[dst], 1);
    g_csr[slot] = make_float4(__int_as_float(src),
                              ea[e * 3], ea[e * 3 + 1], ea[e * 3 + 2]);
}

// ---------------- fused layer-1 GATv2 + layer-2 node transform ---------------
// one warp per (dst node, head) — R8 form (measured best).
__global__ __launch_bounds__(256) void k_gat1(const float* __restrict__ W1e,
                                              const float* __restrict__ att1,
                                              const float* __restrict__ b1,
                                              const float* __restrict__ W2l,
                                              const float* __restrict__ W2r) {
    __shared__ float sW[768];     // W1e (3 x 256)
    __shared__ float sA[256];     // att1
    int tid = threadIdx.x;
    for (int i = tid; i < 768; i += 256) sW[i] = W1e[i];
    if (tid < 256) sA[tid] = att1[tid];
    __syncthreads();

    int gw = blockIdx.x * 8 + (tid >> 5);
    int lane = tid & 31;
    int n = gw >> 2;
    int h = gw & 3;
    if (n >= N_NODES) return;

    int c2 = h * 32 + lane;
    int i = c2 * 2;
    const float w0 = sW[i],     w1 = sW[256 + i],     w2 = sW[512 + i];
    const float w0b = sW[i + 1], w1b = sW[256 + i + 1], w2b = sW[512 + i + 1];
    const float attA = sA[i], attB = sA[i + 1];
    float2 r = reinterpret_cast<const float2*>(g_xr1)[(size_t)n * 128 + c2];

    int start = g_start[n];
    int end   = start + g_deg[n];
    float den = 0.f, ax = 0.f, ay = 0.f;
    for (int idx = start; idx < end; idx++) {
        float4 ent = g_csr[idx];                       // broadcast
        int src = __float_as_int(ent.x);
        float2 l = reinterpret_cast<const float2*>(g_xl1)[(size_t)src * 128 + c2];
        float e0 = ent.y * w0  + ent.z * w1  + ent.w * w2;
        float e1 = ent.y * w0b + ent.z * w1b + ent.w * w2b;
        float m0 = lrelu(l.x + r.x + e0);
        float m1 = lrelu(l.y + r.y + e1);
        float p = warp_sum_all(m0 * attA + m1 * attB);
        float ex = __expf(p);
        den += ex;
        ax += ex * l.x;
        ay += ex * l.y;
    }
    float inv = 1.0f / den;
    float o0 = ax * inv + b1[i];
    float o1 = ay * inv + b1[i + 1];
    o0 = o0 > 0.f ? o0 : (__expf(o0) - 1.f);           // ELU
    o1 = o1 > 0.f ? o1 : (__expf(o1) - 1.f);
    float pl = o0 * W2l[i] + o1 * W2l[i + 1];
    float pr = o0 * W2r[i] + o1 * W2r[i + 1];
    pl = warp_sum(pl);
    pr = warp_sum(pr);
    if (lane == 0) {
        atomicAdd(&g_hl2[n], pl);
        atomicAdd(&g_hr2[n], pr);
    }
}

// ---------------- fused layer-2 GATv2 + scores + exp-sum ----------------
__global__ __launch_bounds__(256) void k_gat2(const float* __restrict__ W2e,
                                              const float* __restrict__ att2,
                                              const float* __restrict__ b2,
                                              float* __restrict__ out) {
    __shared__ float sW[3];
    __shared__ float sAtt, sB2, sSum;
    if (threadIdx.x < 3) sW[threadIdx.x] = W2e[threadIdx.x];
    if (threadIdx.x == 0) { sAtt = att2[0]; sB2 = b2[0]; sSum = 0.f; }
    __syncthreads();

    int n = blockIdx.x * 8 + (threadIdx.x >> 5);
    int lane = threadIdx.x & 31;
    if (n < N_NODES) {
        float hr = g_hr2[n];
        int start = g_start[n];
        int end   = start + g_deg[n];
        float num = 0.f, den = 0.f;
        for (int idx = start + lane; idx < end; idx += 32) {
            float4 ent = g_csr[idx];
            int src = __float_as_int(ent.x);
            float hl = g_hl2[src];
            float m = hl + hr + ent.y * sW[0] + ent.z * sW[1] + ent.w * sW[2];
            float ex = __expf(sAtt * lrelu(m));
            den += ex;
            num += ex * hl;
        }
        num = warp_sum(num);
        den = warp_sum(den);
        if (lane == 0) {
            float s = num / den + sB2;
            g_out2[n] = s;
            out[N_NODES + n] = s;
            atomicAdd(&sSum, __expf(s));
        }
    }
    __syncthreads();
    if (threadIdx.x == 0) atomicAdd(&g_ssum, sSum);
}

// ---------------- final weights (softmax without max-shift; scores O(10)) ----
__global__ void k_weights(float* __restrict__ out) {
    float inv = 1.0f / g_ssum;
    int n = blockIdx.x * blockDim.x + threadIdx.x;
    if (n >= N_NODES) return;
    out[n] = __expf(g_out2[n]) * inv;
}

// ---------------- launch ----------------
extern "C" void kernel_launch(void* const* d_in, const int* in_sizes, int n_in,
                              void* d_out, int out_size) {
    const float* x    = (const float*)d_in[0];
    const float* ea   = (const float*)d_in[1];
    const float* W1l  = (const float*)d_in[2];
    const float* W1r  = (const float*)d_in[3];
    const float* W1e  = (const float*)d_in[4];
    const float* att1 = (const float*)d_in[5];
    const float* b1   = (const float*)d_in[6];
    const float* W2l  = (const float*)d_in[7];
    const float* W2r  = (const float*)d_in[8];
    const float* W2e  = (const float*)d_in[9];
    const float* att2 = (const float*)d_in[10];
    const float* b2   = (const float*)d_in[11];
    const int*   ei   = (const int*)d_in[12];
    float* out = (float*)d_out;

    int ethr_blocks = (N_EDGES + 255) / 256;

    k_zero<<<256, 256>>>();                                  // 1
    k_prep<<<ethr_blocks, 256>>>(ea, ei);                    // 2
    k_scan1<<<N_SCAN_BLK, 256>>>();                          // 3
    dim3 gg(8, (N_NODES + 127) / 128);
    k_gemm<<<gg, 256>>>(x, W1l, W1r);                        // 4 (profiled slot)
    k_scan2<<<1, 256>>>();                                   // 5
    k_scan3<<<(N_NODES + 255) / 256, 256>>>();               // 6
    k_place<<<ethr_blocks, 256>>>(ei, ea);                   // 7
    k_gat1<<<(N_NODES * HEADS + 7) / 8, 256>>>(W1e, att1, b1, W2l, W2r);  // 8
    k_gat2<<<(N_NODES + 7) / 8, 256>>>(W2e, att2, b2, out);  // 9
    k_weights<<<(N_NODES + 255) / 256, 256>>>(out);          // 10
}

// round 15
// speedup vs baseline: 1.2148x; 1.2148x over previous
#include <cuda_runtime.h>
#include <cstdint>

#define N_NODES 50000
#define N_EDGES 800000
#define N_E2    850000      // edges + self loops
#define IN_DIM  128
#define HID     64
#define HEADS   4
#define HC      256         // HEADS*HID
#define NEG_SLOPE 0.2f
#define N_SCAN_BLK 196      // ceil(50000/256)

// ---------------- scratch (device globals; no runtime alloc) ----------------
__device__ float    g_xl1[N_NODES * HC];
__device__ float    g_xr1[N_NODES * HC];
__device__ int      g_deg[N_NODES];
__device__ int      g_start[N_NODES];
__device__ int      g_cursor[N_NODES];
__device__ int      g_blksum[256];
__device__ int      g_blkoff[256];
__device__ float4   g_csr[N_E2];          // {src(bits), a0, a1, a2}
__device__ float    g_hl2[N_NODES];
__device__ float    g_hr2[N_NODES];
__device__ float    g_out2[N_NODES];
__device__ float    g_attr_sum[3];
__device__ float    g_ssum;

// ---------------- helpers ----------------
__device__ __forceinline__ float warp_sum(float v) {
    #pragma unroll
    for (int o = 16; o; o >>= 1) v += __shfl_down_sync(0xffffffffu, v, o);
    return v;
}
__device__ __forceinline__ float warp_sum_all(float v) {
    #pragma unroll
    for (int o = 16; o; o >>= 1) v += __shfl_xor_sync(0xffffffffu, v, o);
    return v;
}
__device__ __forceinline__ float lrelu(float m) {
    return fmaxf(m, NEG_SLOPE * m);
}

// ---------------- init ----------------
__global__ void k_zero() {
    int tid = blockIdx.x * blockDim.x + threadIdx.x;
    int stride = gridDim.x * blockDim.x;
    for (int i = tid; i < N_NODES; i += stride) {
        g_deg[i] = 0; g_hl2[i] = 0.f; g_hr2[i] = 0.f;
    }
    if (tid == 0) {
        g_attr_sum[0] = 0.f; g_attr_sum[1] = 0.f; g_attr_sum[2] = 0.f;
        g_ssum = 0.f;
    }
}

// mean of edge_attr columns (for self-loop fill)
__global__ void k_attr_mean(const float* __restrict__ ea) {
    float s0 = 0.f, s1 = 0.f, s2 = 0.f;
    for (int e = blockIdx.x * blockDim.x + threadIdx.x; e < N_EDGES;
         e += gridDim.x * blockDim.x) {
        s0 += ea[e * 3 + 0]; s1 += ea[e * 3 + 1]; s2 += ea[e * 3 + 2];
    }
    s0 = warp_sum(s0); s1 = warp_sum(s1); s2 = warp_sum(s2);
    if ((threadIdx.x & 31) == 0) {
        atomicAdd(&g_attr_sum[0], s0);
        atomicAdd(&g_attr_sum[1], s1);
        atomicAdd(&g_attr_sum[2], s2);
    }
}

// ---------------- CSR build ----------------
__global__ void k_count(const int* __restrict__ ei) {
    int e = blockIdx.x * blockDim.x + threadIdx.x;
    if (e >= N_E2) return;
    int dst = (e < N_EDGES) ? ei[N_EDGES + e] : e - N_EDGES;
    atomicAdd(&g_deg[dst], 1);
}

// ---------------- SGEMM (R8 form, measured 152.6us): C = A @ B ----------------
// bx<4: C=g_xl1, B=W1l ; bx>=4: C=g_xr1, B=W1r. BM=128 BN=64 BK=16, 8x4/thr.
__global__ __launch_bounds__(256) void k_gemm(const float* __restrict__ A,
                                              const float* __restrict__ W1l,
                                              const float* __restrict__ W1r) {
    __shared__ float As[16][132];
    __shared__ float Bs[16][64];
    const int K = IN_DIM, M = HC;
    int bx = blockIdx.x;
    const float* B = (bx < 4) ? W1l : W1r;
    float* C = (bx < 4) ? g_xl1 : g_xr1;
    int row0 = blockIdx.y * 128, col0 = (bx & 3) * 64;
    int tid = threadIdx.x;
    int tr = tid >> 4, tc = tid & 15;
    float acc[8][4] = {};
    for (int k0 = 0; k0 < K; k0 += 16) {
        #pragma unroll
        for (int i = tid; i < 512; i += 256) {
            int m = i >> 2, kq = (i & 3) * 4;
            int r = row0 + m;
            float4 v = (r < N_NODES)
                ? *reinterpret_cast<const float4*>(&A[(size_t)r * K + k0 + kq])
                : make_float4(0.f, 0.f, 0.f, 0.f);
            As[kq + 0][m] = v.x; As[kq + 1][m] = v.y;
            As[kq + 2][m] = v.z; As[kq + 3][m] = v.w;
        }
        {
            int kk = tid >> 4, nq = (tid & 15) * 4;
            *reinterpret_cast<float4*>(&Bs[kk][nq]) =
                *reinterpret_cast<const float4*>(&B[(size_t)(k0 + kk) * M + col0 + nq]);
        }
        __syncthreads();
        #pragma unroll
        for (int kk = 0; kk < 16; kk++) {
            float4 a0 = *reinterpret_cast<const float4*>(&As[kk][tr * 8]);
            float4 a1 = *reinterpret_cast<const float4*>(&As[kk][tr * 8 + 4]);
            float4 b4 = *reinterpret_cast<const float4*>(&Bs[kk][tc * 4]);
            float a[8] = {a0.x, a0.y, a0.z, a0.w, a1.x, a1.y, a1.z, a1.w};
            float b[4] = {b4.x, b4.y, b4.z, b4.w};
            #pragma unroll
            for (int u = 0; u < 8; u++)
                #pragma unroll
                for (int v = 0; v < 4; v++)
                    acc[u][v] += a[u] * b[v];
        }
        __syncthreads();
    }
    #pragma unroll
    for (int u = 0; u < 8; u++) {
        int r = row0 + tr * 8 + u;
        if (r < N_NODES)
            *reinterpret_cast<float4*>(&C[(size_t)r * M + col0 + tc * 4]) =
                make_float4(acc[u][0], acc[u][1], acc[u][2], acc[u][3]);
    }
}

// parallel scan, stage 1
__global__ void k_scan1() {
    __shared__ int wTot[8];
    int tid = threadIdx.x, lane = tid & 31, wid = tid >> 5;
    int i = blockIdx.x * 256 + tid;
    int v = (i < N_NODES) ? g_deg[i] : 0;
    int x = v;
    #pragma unroll
    for (int o = 1; o < 32; o <<= 1) {
        int t = __shfl_up_sync(0xffffffffu, x, o);
        if (lane >= o) x += t;
    }
    if (lane == 31) wTot[wid] = x;
    __syncthreads();
    if (tid == 0) {
        int s = 0;
        #pragma unroll
        for (int j = 0; j < 8; j++) { int t = wTot[j]; wTot[j] = s; s += t; }
        g_blksum[blockIdx.x] = s;
    }
    __syncthreads();
    if (i < N_NODES) g_start[i] = x - v + wTot[wid];
}

// stage 2
__global__ void k_scan2() {
    __shared__ int wTot[8];
    int tid = threadIdx.x, lane = tid & 31, wid = tid >> 5;
    int v = (tid < N_SCAN_BLK) ? g_blksum[tid] : 0;
    int x = v;
    #pragma unroll
    for (int o = 1; o < 32; o <<= 1) {
        int t = __shfl_up_sync(0xffffffffu, x, o);
        if (lane >= o) x += t;
    }
    if (lane == 31) wTot[wid] = x;
    __syncthreads();
    if (tid == 0) {
        int s = 0;
        #pragma unroll
        for (int j = 0; j < 8; j++) { int t = wTot[j]; wTot[j] = s; s += t; }
    }
    __syncthreads();
    g_blkoff[tid] = x - v + wTot[wid];
}

// stage 3: add block offsets
__global__ void k_scan3() {
    int i = blockIdx.x * blockDim.x + threadIdx.x;
    if (i >= N_NODES) return;
    int s = g_start[i] + g_blkoff[i >> 8];
    g_start[i] = s;
    g_cursor[i] = s;
}

// place packed entries {src, a0, a1, a2}
__global__ void k_place(const int* __restrict__ ei, const float* __restrict__ ea) {
    int e = blockIdx.x * blockDim.x + threadIdx.x;
    if (e >= N_E2) return;
    int src, dst; float a0, a1, a2;
    if (e < N_EDGES) {
        src = ei[e]; dst = ei[N_EDGES + e];
        a0 = ea[e * 3]; a1 = ea[e * 3 + 1]; a2 = ea[e * 3 + 2];
    } else {
        src = dst = e - N_EDGES;
        const float invE = 1.0f / N_EDGES;
        a0 = g_attr_sum[0] * invE; a1 = g_attr_sum[1] * invE; a2 = g_attr_sum[2] * invE;
    }
    int slot = atomicAdd(&g_cursor[dst], 1);
    g_csr[slot] = make_float4(__int_as_float(src), a0, a1, a2);
}

// ---------------- fused layer-1 GATv2 + layer-2 node transform ---------------
// one warp per (dst node, head) — R8 form (measured best).
__global__ __launch_bounds__(256) void k_gat1(const float* __restrict__ W1e,
                                              const float* __restrict__ att1,
                                              const float* __restrict__ b1,
                                              const float* __restrict__ W2l,
                                              const float* __restrict__ W2r) {
    __shared__ float sW[768];     // W1e (3 x 256)
    __shared__ float sA[256];     // att1
    int tid = threadIdx.x;
    for (int i = tid; i < 768; i += 256) sW[i] = W1e[i];
    if (tid < 256) sA[tid] = att1[tid];
    __syncthreads();

    int gw = blockIdx.x * 8 + (tid >> 5);
    int lane = tid & 31;
    int n = gw >> 2;
    int h = gw & 3;
    if (n >= N_NODES) return;

    int c2 = h * 32 + lane;
    int i = c2 * 2;
    const float w0 = sW[i],     w1 = sW[256 + i],     w2 = sW[512 + i];
    const float w0b = sW[i + 1], w1b = sW[256 + i + 1], w2b = sW[512 + i + 1];
    const float attA = sA[i], attB = sA[i + 1];
    float2 r = reinterpret_cast<const float2*>(g_xr1)[(size_t)n * 128 + c2];

    int start = g_start[n];
    int end   = start + g_deg[n];
    float den = 0.f, ax = 0.f, ay = 0.f;
    for (int idx = start; idx < end; idx++) {
        float4 ent = g_csr[idx];                       // broadcast
        int src = __float_as_int(ent.x);
        float2 l = reinterpret_cast<const float2*>(g_xl1)[(size_t)src * 128 + c2];
        float e0 = ent.y * w0  + ent.z * w1  + ent.w * w2;
        float e1 = ent.y * w0b + ent.z * w1b + ent.w * w2b;
        float m0 = lrelu(l.x + r.x + e0);
        float m1 = lrelu(l.y + r.y + e1);
        float p = warp_sum_all(m0 * attA + m1 * attB);
        float ex = __expf(p);
        den += ex;
        ax += ex * l.x;
        ay += ex * l.y;
    }
    float inv = 1.0f / den;
    float o0 = ax * inv + b1[i];
    float o1 = ay * inv + b1[i + 1];
    o0 = o0 > 0.f ? o0 : (__expf(o0) - 1.f);           // ELU
    o1 = o1 > 0.f ? o1 : (__expf(o1) - 1.f);
    float pl = o0 * W2l[i] + o1 * W2l[i + 1];
    float pr = o0 * W2r[i] + o1 * W2r[i + 1];
    pl = warp_sum(pl);
    pr = warp_sum(pr);
    if (lane == 0) {
        atomicAdd(&g_hl2[n], pl);
        atomicAdd(&g_hr2[n], pr);
    }
}

// ---------------- fused layer-2 GATv2 + scores + exp-sum ----------------
__global__ __launch_bounds__(256) void k_gat2(const float* __restrict__ W2e,
                                              const float* __restrict__ att2,
                                              const float* __restrict__ b2,
                                              float* __restrict__ out) {
    __shared__ float sW[3];
    __shared__ float sAtt, sB2, sSum;
    if (threadIdx.x < 3) sW[threadIdx.x] = W2e[threadIdx.x];
    if (threadIdx.x == 0) { sAtt = att2[0]; sB2 = b2[0]; sSum = 0.f; }
    __syncthreads();

    int n = blockIdx.x * 8 + (threadIdx.x >> 5);
    int lane = threadIdx.x & 31;
    if (n < N_NODES) {
        float hr = g_hr2[n];
        int start = g_start[n];
        int end   = start + g_deg[n];
        float num = 0.f, den = 0.f;
        for (int idx = start + lane; idx < end; idx += 32) {
            float4 ent = g_csr[idx];
            int src = __float_as_int(ent.x);
            float hl = g_hl2[src];
            float m = hl + hr + ent.y * sW[0] + ent.z * sW[1] + ent.w * sW[2];
            float ex = __expf(sAtt * lrelu(m));
            den += ex;
            num += ex * hl;
        }
        num = warp_sum(num);
        den = warp_sum(den);
        if (lane == 0) {
            float s = num / den + sB2;
            g_out2[n] = s;
            out[N_NODES + n] = s;
            atomicAdd(&sSum, __expf(s));
        }
    }
    __syncthreads();
    if (threadIdx.x == 0) atomicAdd(&g_ssum, sSum);
}

// ---------------- final weights (softmax without max-shift; scores O(10)) ----
__global__ void k_weights(float* __restrict__ out) {
    float inv = 1.0f / g_ssum;
    int n = blockIdx.x * blockDim.x + threadIdx.x;
    if (n >= N_NODES) return;
    out[n] = __expf(g_out2[n]) * inv;
}

// ---------------- launch ----------------
extern "C" void kernel_launch(void* const* d_in, const int* in_sizes, int n_in,
                              void* d_out, int out_size) {
    const float* x    = (const float*)d_in[0];
    const float* ea   = (const float*)d_in[1];
    const float* W1l  = (const float*)d_in[2];
    const float* W1r  = (const float*)d_in[3];
    const float* W1e  = (const float*)d_in[4];
    const float* att1 = (const float*)d_in[5];
    const float* b1   = (const float*)d_in[6];
    const float* W2l  = (const float*)d_in[7];
    const float* W2r  = (const float*)d_in[8];
    const float* W2e  = (const float*)d_in[9];
    const float* att2 = (const float*)d_in[10];
    const float* b2   = (const float*)d_in[11];
    const int*   ei   = (const int*)d_in[12];
    float* out = (float*)d_out;

    int ethr_blocks = (N_E2 + 255) / 256;

    k_zero<<<256, 256>>>();                                  // 1
    k_attr_mean<<<256, 256>>>(ea);                           // 2
    k_count<<<ethr_blocks, 256>>>(ei);                       // 3
    dim3 gg(8, (N_NODES + 127) / 128);
    k_gemm<<<gg, 256>>>(x, W1l, W1r);                        // 4 (profiled slot)
    k_scan1<<<N_SCAN_BLK, 256>>>();                          // 5
    k_scan2<<<1, 256>>>();                                   // 6
    k_scan3<<<(N_NODES + 255) / 256, 256>>>();               // 7
    k_place<<<ethr_blocks, 256>>>(ei, ea);                   // 8
    k_gat1<<<(N_NODES * HEADS + 7) / 8, 256>>>(W1e, att1, b1, W2l, W2r);  // 9
    k_gat2<<<(N_NODES + 7) / 8, 256>>>(W2e, att2, b2, out);  // 10
    k_weights<<<(N_NODES + 255) / 256, 256>>>(out);          // 11
}